// round 15
// baseline (speedup 1.0000x reference)
#include <cuda_runtime.h>
#include <cstdint>

// Correlation1D band-GEMM, single-pass TF32 (mma.m16n8k8.tf32).
// R15 = R14 with 12 m16 warps (384 thr): acc 48 regs/thread -> ~85 regs ->
// 2 CTAs/SM = 24 warps/SM for latency hiding. Fragments built by scalar LDS
// directly from fp32 cp.async stages (3-slot ring); one sync per chunk.
// out[b,d,h,w] = (1/256)*sum_c in1[b,c,h,w]*in2pad[b,c,h,w+d-40]

#define Bn 8
#define Cn 256
#define Hn 96
#define Wn 192
#define Dn 81
#define PADn 40
#define HWn (Hn * Wn)

#define NTHREADS 384
#define KC 16
#define NCHUNK (Cn / KC)          // 16

#define SAROWF 196                // A stage row floats
#define SAROWB (SAROWF * 4)       // 784
#define SABYTES (KC * SAROWB)     // 12544
#define SBROWF 280                // B stage row floats (280%32=24 -> B frags conflict-free)
#define SBROWB (SBROWF * 4)       // 1120
#define SBBYTES (KC * SBROWB)     // 17920
#define STPAIR (SABYTES + SBBYTES) // 30464

#define SMEM_USED (3 * STPAIR)    // 91392 (epilogue outT 62208 reuses this)
#define DYNSMEM (SMEM_USED + 1024)

static __device__ __forceinline__ uint32_t smem_u32(const void* p) {
    uint32_t a;
    asm("{ .reg .u64 t; cvta.to.shared.u64 t, %1; cvt.u32.u64 %0, t; }" : "=r"(a) : "l"(p));
    return a;
}

static __device__ __forceinline__ void cp_async16(uint32_t dst, const void* src) {
    asm volatile("cp.async.cg.shared.global [%0], [%1], 16;" :: "r"(dst), "l"(src) : "memory");
}

static __device__ __forceinline__ uint32_t f2tf32(float f) {
    uint32_t r;
    asm("cvt.rna.tf32.f32 %0, %1;" : "=r"(r) : "f"(f));
    return r;
}

#define MMA_TF32(a4, A, b0, b1)                                                \
    asm volatile("mma.sync.aligned.m16n8k8.row.col.f32.tf32.tf32.f32 "         \
        "{%0,%1,%2,%3}, {%4,%5,%6,%7}, {%8,%9}, {%0,%1,%2,%3};"                \
        : "+f"((a4)[0]), "+f"((a4)[1]), "+f"((a4)[2]), "+f"((a4)[3])           \
        : "r"((A)[0]), "r"((A)[1]), "r"((A)[2]), "r"((A)[3]), "r"(b0), "r"(b1))

__global__ __launch_bounds__(NTHREADS, 2)
void corr1d_t2_kernel(const float* __restrict__ in1,
                      const float* __restrict__ in2,
                      float* __restrict__ out) {
    extern __shared__ char dsm_raw[];
    const uint32_t dsm_addr = smem_u32(dsm_raw);
    const uint32_t base_u = (dsm_addr + 1023u) & ~1023u;
    char* smp = dsm_raw + (base_u - dsm_addr);

    const int h = blockIdx.x;
    const int b = blockIdx.y;
    const int tid = threadIdx.x;
    const int wid = tid >> 5;
    const int lane = tid & 31;

    const float* a_src = in1 + (size_t)b * Cn * HWn + (size_t)h * Wn;
    const float* b_src = in2 + (size_t)b * Cn * HWn + (size_t)h * Wn;

    // ---- cp.async per-thread constants: 4 ops/thread (2 A + 2 B rows) ----
    const int iq16 = (tid % 48) * 16;      // byte offset of 16B run within a row
    const int ikr = tid / 48;              // base k row 0..7 (k = ikr + 8j)
    const float* a_tsrc = a_src + (size_t)ikr * HWn + (iq16 >> 2);
    const float* b_tsrc = b_src + (size_t)ikr * HWn + (iq16 >> 2);
    const uint32_t a_dst0 = (uint32_t)(ikr * SAROWB + iq16);
    const uint32_t b_dst0 = (uint32_t)(ikr * SBROWB + PADn * 4 + iq16);

    // ---- zero B-stage pad cols (u<40, u in [232,280)) in all 3 ring slots ----
    for (int t = tid; t < 3 * KC * 22; t += NTHREADS) {
        const int sl = t / (KC * 22);
        const int r = (t % (KC * 22)) / 22;
        const int jj = t % 22;
        const uint32_t off = (jj < 10) ? (uint32_t)(jj * 16)
                                       : (uint32_t)(232 * 4 + (jj - 10) * 16);
        *(uint4*)(smp + sl * STPAIR + SABYTES + r * SBROWB + off) = make_uint4(0, 0, 0, 0);
    }

    float acc[12][4];
#pragma unroll
    for (int n = 0; n < 12; ++n)
#pragma unroll
        for (int i = 0; i < 4; ++i) acc[n][i] = 0.0f;

    // ---- fragment-LDS per-thread byte offsets (within a ring slot) ----
    const int w0 = wid * 16;
    // A m16k8 frag: a0=A[k=l&3][m=l>>2], a1=m+8, a2=k+4, a3=both
    const uint32_t a_fr = (uint32_t)((lane & 3) * SAROWB + 4 * (w0 + (lane >> 2)));
    // B n8k8 frag: b0=B[k=l&3][n=l>>2], b1=k+4;  n -> stage col u0+(l>>2)
    const uint32_t b_fr = (uint32_t)(SABYTES + (lane & 3) * SBROWB + 4 * (w0 + (lane >> 2)));

    auto issue = [&](int ch, int sl) {
        const uint32_t stA = base_u + (uint32_t)sl * STPAIR + a_dst0;
        const uint32_t stB = base_u + (uint32_t)sl * STPAIR + SABYTES + b_dst0;
        const size_t co = (size_t)ch * KC * HWn;
        const float* pa = a_tsrc + co;
        const float* pb = b_tsrc + co;
#pragma unroll
        for (int j = 0; j < 2; ++j) {
            cp_async16(stA + j * (8 * SAROWB), pa + (size_t)(8 * j) * HWn);
            cp_async16(stB + j * (8 * SBROWB), pb + (size_t)(8 * j) * HWn);
        }
        asm volatile("cp.async.commit_group;" ::: "memory");
    };

    issue(0, 0);
    issue(1, 1);
    asm volatile("cp.async.wait_group 1;" ::: "memory");   // chunk 0 complete
    __syncthreads();                                        // + pad zeros visible

    int csl = 0, isl = 2;
    for (int i = 0; i < NCHUNK; ++i) {
        if (i + 2 < NCHUNK) issue(i + 2, isl);

        // ---- compute chunk i directly from stage slot csl ----
        {
            const char* sp = smp + csl * STPAIR;
#pragma unroll
            for (int s = 0; s < 2; ++s) {
                const char* spA = sp + s * (8 * SAROWB);
                const char* spB = sp + s * (8 * SBROWB);
                uint32_t A0[4];
                A0[0] = f2tf32(*(const float*)(spA + a_fr));
                A0[1] = f2tf32(*(const float*)(spA + a_fr + 32));
                A0[2] = f2tf32(*(const float*)(spA + a_fr + 4 * SAROWB));
                A0[3] = f2tf32(*(const float*)(spA + a_fr + 4 * SAROWB + 32));
#pragma unroll
                for (int tj = 0; tj < 12; ++tj) {
                    const uint32_t bo = b_fr + (uint32_t)(tj * 32);
                    const uint32_t b0 = f2tf32(*(const float*)(spB + bo));
                    const uint32_t b1 = f2tf32(*(const float*)(spB + bo + 4 * SBROWB));
                    MMA_TF32(acc[tj], A0, b0, b1);
                }
            }
        }

        if (i + 2 < NCHUNK) {
            asm volatile("cp.async.wait_group 1;" ::: "memory");
        } else {
            asm volatile("cp.async.wait_group 0;" ::: "memory");
        }
        __syncthreads();   // stage(i+1) ready; all reads of slot csl done

        csl = (csl == 2) ? 0 : csl + 1;
        isl = (isl == 2) ? 0 : isl + 1;
    }

    // ---- epilogue: band extraction into smem, then coalesced store ----
    float* outT = (float*)smp;  // [81][192] f32 over the (now dead) stages
    const float scale = 1.0f / (float)Cn;
    const int r_ = lane >> 2;
    const int col2 = (lane & 3) * 2;
#pragma unroll
    for (int tj = 0; tj < 12; ++tj) {
#pragma unroll
        for (int half = 0; half < 2; ++half) {
            const int mrow = r_ + half * 8;
            const int w = w0 + mrow;
#pragma unroll
            for (int e = 0; e < 2; ++e) {
                const int d = 8 * tj + col2 + e - mrow;
                if (d >= 0 && d < Dn) {
                    outT[d * Wn + w] = acc[tj][half * 2 + e] * scale;
                }
            }
        }
    }
    __syncthreads();

    for (int t = tid; t < Dn * (Wn / 4); t += NTHREADS) {
        const int d = t / (Wn / 4);
        const int q = t % (Wn / 4);
        const float4 v = ((const float4*)outT)[d * (Wn / 4) + q];
        *(float4*)(out + (((size_t)b * Dn + d) * Hn + h) * Wn + q * 4) = v;
    }
}

extern "C" void kernel_launch(void* const* d_in, const int* in_sizes, int n_in,
                              void* d_out, int out_size) {
    const float* in1 = (const float*)d_in[0];
    const float* in2 = (const float*)d_in[1];
    float* out = (float*)d_out;
    cudaFuncSetAttribute(corr1d_t2_kernel, cudaFuncAttributeMaxDynamicSharedMemorySize, DYNSMEM);
    dim3 grid(Hn, Bn);   // (96, 8)
    corr1d_t2_kernel<<<grid, NTHREADS, DYNSMEM>>>(in1, in2, out);
}

// round 16
// speedup vs baseline: 1.7368x; 1.7368x over previous
#include <cuda_runtime.h>
#include <cstdint>

// Correlation1D band-GEMM, single-pass TF32 (mma.m16n8k8.tf32).
// R16 = R14 (6 m32 warps, 3-slot cp.async ring, frag-LDS direct from fp32
// stages) with NO cvt.rna.tf32: raw fp32 bits are fed to the tf32 MMA
// (hardware reads bits[31:13] -> effective RZ tf32). Removes ~72 CVTs per
// warp-chunk and one dependent ALU stage from every LDS->MMA chain.
// out[b,d,h,w] = (1/256)*sum_c in1[b,c,h,w]*in2pad[b,c,h,w+d-40]

#define Bn 8
#define Cn 256
#define Hn 96
#define Wn 192
#define Dn 81
#define PADn 40
#define HWn (Hn * Wn)

#define NTHREADS 192
#define KC 16
#define NCHUNK (Cn / KC)          // 16

#define SAROWF 196                // A stage row floats (192 used)
#define SAROWB (SAROWF * 4)       // 784
#define SABYTES (KC * SAROWB)     // 12544
#define SBROWF 280                // B stage row floats (280%32=24 -> frags conflict-free)
#define SBROWB (SBROWF * 4)       // 1120
#define SBBYTES (KC * SBROWB)     // 17920
#define STPAIR (SABYTES + SBBYTES) // 30464

#define SMEM_USED (3 * STPAIR)    // 91392 (epilogue outT 62208 reuses this)
#define DYNSMEM (SMEM_USED + 1024)

static __device__ __forceinline__ uint32_t smem_u32(const void* p) {
    uint32_t a;
    asm("{ .reg .u64 t; cvta.to.shared.u64 t, %1; cvt.u32.u64 %0, t; }" : "=r"(a) : "l"(p));
    return a;
}

static __device__ __forceinline__ void cp_async16(uint32_t dst, const void* src) {
    asm volatile("cp.async.cg.shared.global [%0], [%1], 16;" :: "r"(dst), "l"(src) : "memory");
}

#define MMA_TF32(a4, A, b0, b1)                                                \
    asm volatile("mma.sync.aligned.m16n8k8.row.col.f32.tf32.tf32.f32 "         \
        "{%0,%1,%2,%3}, {%4,%5,%6,%7}, {%8,%9}, {%0,%1,%2,%3};"                \
        : "+f"((a4)[0]), "+f"((a4)[1]), "+f"((a4)[2]), "+f"((a4)[3])           \
        : "r"((A)[0]), "r"((A)[1]), "r"((A)[2]), "r"((A)[3]), "r"(b0), "r"(b1))

__global__ __launch_bounds__(NTHREADS, 2)
void corr1d_t3_kernel(const float* __restrict__ in1,
                      const float* __restrict__ in2,
                      float* __restrict__ out) {
    extern __shared__ char dsm_raw[];
    const uint32_t dsm_addr = smem_u32(dsm_raw);
    const uint32_t base_u = (dsm_addr + 1023u) & ~1023u;
    char* smp = dsm_raw + (base_u - dsm_addr);

    const int h = blockIdx.x;
    const int b = blockIdx.y;
    const int tid = threadIdx.x;
    const int wid = tid >> 5;
    const int lane = tid & 31;

    const float* a_src = in1 + (size_t)b * Cn * HWn + (size_t)h * Wn;
    const float* b_src = in2 + (size_t)b * Cn * HWn + (size_t)h * Wn;

    // ---- cp.async per-thread constants: 8 ops/thread (4 A + 4 B rows) ----
    const int iq16 = (tid % 48) * 16;
    const int ikr = tid / 48;              // base k row 0..3 (k = ikr + 4j)
    const float* a_tsrc = a_src + (size_t)ikr * HWn + (iq16 >> 2);
    const float* b_tsrc = b_src + (size_t)ikr * HWn + (iq16 >> 2);
    const uint32_t a_dst0 = (uint32_t)(ikr * SAROWB + iq16);
    const uint32_t b_dst0 = (uint32_t)(ikr * SBROWB + PADn * 4 + iq16);

    // ---- zero B-stage pad cols (u<40, u in [232,280)) in all 3 ring slots ----
    for (int t = tid; t < 3 * KC * 22; t += NTHREADS) {
        const int sl = t / (KC * 22);
        const int r = (t % (KC * 22)) / 22;
        const int jj = t % 22;
        const uint32_t off = (jj < 10) ? (uint32_t)(jj * 16)
                                       : (uint32_t)(232 * 4 + (jj - 10) * 16);
        *(uint4*)(smp + sl * STPAIR + SABYTES + r * SBROWB + off) = make_uint4(0, 0, 0, 0);
    }

    float acc[24][4];
#pragma unroll
    for (int n = 0; n < 24; ++n)
#pragma unroll
        for (int i = 0; i < 4; ++i) acc[n][i] = 0.0f;

    // ---- fragment-LDS per-thread byte offsets (within a ring slot) ----
    const int w0 = wid * 32;
    const uint32_t a_fr = (uint32_t)((lane & 3) * SAROWB + 4 * (w0 + (lane >> 2)));
    const uint32_t b_fr = (uint32_t)(SABYTES + (lane & 3) * SBROWB + 4 * (w0 + (lane >> 2)));

    auto issue = [&](int ch, int sl) {
        const uint32_t stA = base_u + (uint32_t)sl * STPAIR + a_dst0;
        const uint32_t stB = base_u + (uint32_t)sl * STPAIR + SABYTES + b_dst0;
        const size_t co = (size_t)ch * KC * HWn;
        const float* pa = a_tsrc + co;
        const float* pb = b_tsrc + co;
#pragma unroll
        for (int j = 0; j < 4; ++j) {
            cp_async16(stA + j * (4 * SAROWB), pa + (size_t)(4 * j) * HWn);
            cp_async16(stB + j * (4 * SBROWB), pb + (size_t)(4 * j) * HWn);
        }
        asm volatile("cp.async.commit_group;" ::: "memory");
    };

    issue(0, 0);
    issue(1, 1);
    asm volatile("cp.async.wait_group 1;" ::: "memory");   // chunk 0 complete
    __syncthreads();                                        // + pad zeros visible

    int csl = 0, isl = 2;
    for (int i = 0; i < NCHUNK; ++i) {
        if (i + 2 < NCHUNK) issue(i + 2, isl);

        // ---- compute chunk i directly from stage slot csl (raw fp32 bits) ----
        {
            const char* sp = smp + csl * STPAIR;
#pragma unroll
            for (int s = 0; s < 2; ++s) {
                const char* spA = sp + s * (8 * SAROWB);
                const char* spB = sp + s * (8 * SBROWB);
                uint32_t A0[4], A1[4];
#pragma unroll
                for (int q = 0; q < 4; ++q) {
                    const uint32_t o = a_fr + (uint32_t)((q >> 1) * (4 * SAROWB) + (q & 1) * 32);
                    A0[q] = *(const uint32_t*)(spA + o);
                    A1[q] = *(const uint32_t*)(spA + o + 64);
                }
#pragma unroll
                for (int tj = 0; tj < 14; ++tj) {
                    const uint32_t bo = b_fr + (uint32_t)(tj * 32);
                    const uint32_t b0 = *(const uint32_t*)(spB + bo);
                    const uint32_t b1 = *(const uint32_t*)(spB + bo + 4 * SBROWB);
                    if (tj < 12) MMA_TF32(acc[tj], A0, b0, b1);
                    if (tj >= 2) MMA_TF32(acc[12 + tj - 2], A1, b0, b1);
                }
            }
        }

        if (i + 2 < NCHUNK) {
            asm volatile("cp.async.wait_group 1;" ::: "memory");
        } else {
            asm volatile("cp.async.wait_group 0;" ::: "memory");
        }
        __syncthreads();   // stage(i+1) ready; all reads of slot csl done

        csl = (csl == 2) ? 0 : csl + 1;
        isl = (isl == 2) ? 0 : isl + 1;
    }

    // ---- epilogue: band extraction into smem, then coalesced store ----
    float* outT = (float*)smp;  // [81][192] f32 over the (now dead) stages
    const float scale = 1.0f / (float)Cn;
    const int r_ = lane >> 2;
    const int col2 = (lane & 3) * 2;
#pragma unroll
    for (int ai = 0; ai < 24; ++ai) {
        const int mt = ai / 12;
        const int tg = (ai % 12) + 2 * mt;
#pragma unroll
        for (int half = 0; half < 2; ++half) {
            const int mrow = 16 * mt + r_ + half * 8;
            const int w = w0 + mrow;
#pragma unroll
            for (int e = 0; e < 2; ++e) {
                const int d = 8 * tg + col2 + e - mrow;
                if (d >= 0 && d < Dn) {
                    outT[d * Wn + w] = acc[ai][half * 2 + e] * scale;
                }
            }
        }
    }
    __syncthreads();

    for (int t = tid; t < Dn * (Wn / 4); t += NTHREADS) {
        const int d = t / (Wn / 4);
        const int q = t % (Wn / 4);
        const float4 v = ((const float4*)outT)[d * (Wn / 4) + q];
        *(float4*)(out + (((size_t)b * Dn + d) * Hn + h) * Wn + q * 4) = v;
    }
}

extern "C" void kernel_launch(void* const* d_in, const int* in_sizes, int n_in,
                              void* d_out, int out_size) {
    const float* in1 = (const float*)d_in[0];
    const float* in2 = (const float*)d_in[1];
    float* out = (float*)d_out;
    cudaFuncSetAttribute(corr1d_t3_kernel, cudaFuncAttributeMaxDynamicSharedMemorySize, DYNSMEM);
    dim3 grid(Hn, Bn);   // (96, 8)
    corr1d_t3_kernel<<<grid, NTHREADS, DYNSMEM>>>(in1, in2, out);
}